// round 16
// baseline (speedup 1.0000x reference)
#include <cuda_runtime.h>
#include <cuda_fp16.h>
#include <cstdint>

// ---------------------------------------------------------------------------
// Problem dims
// ---------------------------------------------------------------------------
#define BDIM 4096
#define NDIM 2048
#define KDIM 2048
#define DEPTH 7
#define WROWS 2049            // K rows + bias row

// ---------------------------------------------------------------------------
// Tiling: 128x128 CTA tile, 8 warps (32x64 warp tile), K-chunks of 64,
// 3-stage cp.async pipeline, SW128 swizzle, hoisted addresses.
// ONE fused gemm grid (7 layers x 512 tiles) + ONE flat prep kernel.
// ---------------------------------------------------------------------------
#define BLK_M 128
#define BLK_N 128
#define BLK_K 64
#define CHUNKS (KDIM / BLK_K)     // 32
#define STAGES 3

#define TILES_M (BDIM / BLK_M)    // 32
#define TILES_N (NDIM / BLK_N)    // 16
#define TILES_L (TILES_M * TILES_N)  // 512

#define A_BYTES 16384
#define B_SUB_BYTES 8192
#define STAGE_BYTES (A_BYTES + 2 * B_SUB_BYTES)      // 32768
#define SMEM_GEMM (STAGES * STAGE_BYTES)             // 98304
#define SMEM_TOTAL (SMEM_GEMM + 512)                 // + bias tile (128 f32) = 98816

// prep sizes (float4 units)
#define X_F4 (BDIM * NDIM / 4)               // 2097152
#define W_F4_ALL (DEPTH * WROWS * NDIM / 4)  // 7343616
#define PREP_F4 (X_F4 + W_F4_ALL)            // 9440768
#define PREP_PER 4                           // float4 per thread
#define PREP_CTAS ((PREP_F4 + 256 * PREP_PER - 1) / (256 * PREP_PER))  // 9220

// ---------------------------------------------------------------------------
// Device scratch (allocation-free rule)
// ---------------------------------------------------------------------------
__device__ __half g_xH[(size_t)BDIM * NDIM];
__device__ __half g_a[2][(size_t)BDIM * NDIM];
__device__ __half g_Wh[(size_t)DEPTH * WROWS * NDIM];
__device__ int g_ready[DEPTH * TILES_M];   // completed bn-tiles per (layer, bm)

// ---------------------------------------------------------------------------
// helpers
// ---------------------------------------------------------------------------
__device__ __forceinline__ void ldsm4_a(uint32_t (&r)[4], uint32_t addr) {
    asm volatile("ldmatrix.sync.aligned.m8n8.x4.shared.b16 {%0,%1,%2,%3}, [%4];\n"
                 : "=r"(r[0]), "=r"(r[1]), "=r"(r[2]), "=r"(r[3]) : "r"(addr));
}

__device__ __forceinline__ void ldsm4t_a(uint32_t (&r)[4], uint32_t addr) {
    asm volatile("ldmatrix.sync.aligned.m8n8.x4.trans.shared.b16 {%0,%1,%2,%3}, [%4];\n"
                 : "=r"(r[0]), "=r"(r[1]), "=r"(r[2]), "=r"(r[3]) : "r"(addr));
}

__device__ __forceinline__ void mma_f16(float (&d)[4], const uint32_t (&a)[4], const uint32_t* b) {
    asm volatile(
        "mma.sync.aligned.m16n8k16.row.col.f32.f16.f16.f32 "
        "{%0,%1,%2,%3}, {%4,%5,%6,%7}, {%8,%9}, {%0,%1,%2,%3};\n"
        : "+f"(d[0]), "+f"(d[1]), "+f"(d[2]), "+f"(d[3])
        : "r"(a[0]), "r"(a[1]), "r"(a[2]), "r"(a[3]), "r"(b[0]), "r"(b[1]));
}

__device__ __forceinline__ void cp16(uint32_t dst, const void* src) {
    asm volatile("cp.async.cg.shared.global [%0], [%1], 16;" :: "r"(dst), "l"(src));
}
#define CP_COMMIT() asm volatile("cp.async.commit_group;" ::: "memory")
#define CP_WAIT(n)  asm volatile("cp.async.wait_group %0;" :: "n"(n) : "memory")

__device__ __forceinline__ uint2 cvt4(float4 v) {
    __half2 H0 = __floats2half2_rn(v.x, v.y);
    __half2 H1 = __floats2half2_rn(v.z, v.w);
    uint2 u; u.x = *(uint32_t*)&H0; u.y = *(uint32_t*)&H1;
    return u;
}

// ---------------------------------------------------------------------------
// Prep kernel: zero flags (CTA 0) + convert x and all W layers to fp16.
// Grid-stride, 4 float4/thread, evict-first loads (single-use fp32 stream).
// ---------------------------------------------------------------------------
__global__ void prep_kernel(const float4* __restrict__ xF,
                            const float4* __restrict__ Wfp) {
    const int tid = threadIdx.x;
    if (blockIdx.x == 0 && tid < DEPTH * TILES_M)
        g_ready[tid] = 0;

    const int base = (blockIdx.x * 256) * PREP_PER + tid;
#pragma unroll
    for (int q = 0; q < PREP_PER; q++) {
        const int i = base + q * 256;
        if (i < X_F4) {
            reinterpret_cast<uint2*>(g_xH)[i] = cvt4(__ldcs(xF + i));
        } else if (i < PREP_F4) {
            const int j = i - X_F4;
            reinterpret_cast<uint2*>(g_Wh)[j] = cvt4(__ldcs(Wfp + j));
        }
    }
}

// ---------------------------------------------------------------------------
// Fused 7-layer gemm kernel. CTA bid -> (layer, bm, bn).
// ---------------------------------------------------------------------------
__global__ __launch_bounds__(256, 2)
void fused_mlp_kernel(const __half* __restrict__ xH,
                      __half* __restrict__ act,      // [2][B*N]
                      const __half* __restrict__ Wh, // [DEPTH][WROWS][N]
                      const float* __restrict__ Wfp, // original fp32 W (for bias)
                      float* __restrict__ outF)
{
    extern __shared__ __align__(128) __half smem[];
    const uint32_t sb = (uint32_t)__cvta_generic_to_shared(smem);

    const int bid = blockIdx.x;
    const int layer = bid >> 9;          // /512
    const int t = bid & 511;
    const int bm = t >> 4;               // 0..31
    const int bn = t & 15;               // 0..15
    const int is_last = (layer == DEPTH - 1);

    const size_t ACT = (size_t)BDIM * NDIM;
    const __half* A = (layer == 0) ? xH : act + ((size_t)((layer - 1) & 1)) * ACT;
    __half* nextA = act + ((size_t)(layer & 1)) * ACT;
    const __half* B = Wh + (size_t)layer * WROWS * NDIM;
    const float* bias = Wfp + (size_t)layer * WROWS * NDIM + (size_t)KDIM * NDIM;

    const int tid = threadIdx.x;
    const int lane = tid & 31;
    const int warp = tid >> 5;
    const int warp_m = warp >> 1;   // 0..3 (32 rows)
    const int warp_n = warp & 1;    // 0..1 (64 cols -> B subtile)

    // ---------------- wait for input rowblock (layers > 0) ----------------
    if (layer > 0) {
        if (tid == 0) {
            volatile int* cnt = &g_ready[(layer - 1) * TILES_M + bm];
            while (*cnt < TILES_N) __nanosleep(128);
            __threadfence();
        }
        __syncthreads();
    }

    // ---------------- bias tile -> smem (bit-identical fp32 values) --------
    float* biasS = (float*)((char*)smem + SMEM_GEMM);
    if (tid < BLK_N) biasS[tid] = __ldg(bias + bn * BLK_N + tid);

    // ---------------- precomputed cp.async addresses ----------------
    const int a_row = tid >> 1;
    const int a_gb16 = (tid & 1) * 64;
    const uint32_t a_xor = (uint32_t)((a_row & 7) << 4);
    const uint32_t dstA0 = sb + (uint32_t)(a_row * 128) + (uint32_t)(a_gb16 ^ a_xor);
    const __half* gA = A + (size_t)(bm * BLK_M + a_row) * KDIM + (tid & 1) * 32;

    const int b_r0 = tid >> 4;
    const int b_gc = tid & 15;
    const uint32_t b_xor = (uint32_t)((b_r0 & 7) << 4);
    const uint32_t dstB0 = sb + (uint32_t)A_BYTES + (uint32_t)((b_gc >> 3) * B_SUB_BYTES)
                         + (uint32_t)(b_r0 * 128) + ((uint32_t)((b_gc & 7) * 16) ^ b_xor);
    const __half* gB = B + (size_t)b_r0 * NDIM + bn * BLK_N + b_gc * 8;

    auto load_stage = [&](int s, const __half* gA_c, const __half* gB_c) {
        const uint32_t sbase = (uint32_t)(s * STAGE_BYTES);
#pragma unroll
        for (int q = 0; q < 4; q++)
            cp16((dstA0 ^ (uint32_t)(q * 16)) + sbase, gA_c + q * 8);
#pragma unroll
        for (int p = 0; p < 4; p++)
            cp16(dstB0 + sbase + (uint32_t)(p * 2048), gB_c + (size_t)(p * 16) * NDIM);
        CP_COMMIT();
    };

    // ---------------- ldsm base addresses (stage-relative) ----------------
    const uint32_t hi16 = (uint32_t)((lane >> 4) << 4);
    uint32_t aAddr[2];
#pragma unroll
    for (int mi = 0; mi < 2; mi++) {
        const int r = warp_m * 32 + mi * 16 + (lane & 15);
        aAddr[mi] = sb + (uint32_t)(r * 128) + (hi16 ^ (uint32_t)((r & 7) << 4));
    }
    const uint32_t bAddr0 = sb + (uint32_t)A_BYTES + (uint32_t)(warp_n * B_SUB_BYTES)
                          + (uint32_t)((lane & 15) * 128)
                          + (hi16 ^ (uint32_t)((lane & 7) << 4));

    float acc[2][8][4];
#pragma unroll
    for (int i = 0; i < 2; i++)
#pragma unroll
        for (int j = 0; j < 8; j++)
#pragma unroll
            for (int k = 0; k < 4; k++) acc[i][j][k] = 0.f;

    auto compute_stage = [&](int s) {
        const uint32_t sbase = (uint32_t)(s * STAGE_BYTES);
#pragma unroll
        for (int kk = 0; kk < 4; kk++) {
            uint32_t ah[2][4];
#pragma unroll
            for (int mi = 0; mi < 2; mi++)
                ldsm4_a(ah[mi], (aAddr[mi] ^ (uint32_t)(kk << 5)) + sbase);
#pragma unroll
            for (int ng = 0; ng < 4; ng++) {
                uint32_t bh[4];
                ldsm4t_a(bh, (bAddr0 ^ (uint32_t)(ng << 5)) + sbase + (uint32_t)(kk * 2048));
#pragma unroll
                for (int mi = 0; mi < 2; mi++)
#pragma unroll
                    for (int h = 0; h < 2; h++)
                        mma_f16(acc[mi][ng * 2 + h], ah[mi], &bh[h * 2]);
            }
        }
    };

    // ---------------- 3-stage pipeline ----------------
    const __half* gA_c = gA;
    const __half* gB_c = gB;
    load_stage(0, gA_c, gB_c);
    gA_c += BLK_K; gB_c += (size_t)BLK_K * NDIM;
    load_stage(1, gA_c, gB_c);
    gA_c += BLK_K; gB_c += (size_t)BLK_K * NDIM;
#pragma unroll 1
    for (int c = 0; c < CHUNKS; c++) {
        CP_WAIT(1);
        __syncthreads();
        compute_stage(c % STAGES);
        if (c + 2 < CHUNKS) {
            load_stage((c + 2) % STAGES, gA_c, gB_c);
            gA_c += BLK_K; gB_c += (size_t)BLK_K * NDIM;
        }
    }

    // ---------------- epilogue: bias(smem) + ReLU + store ----------------
    const int row0 = bm * BLK_M + warp_m * 32 + (lane >> 2);
    const int cl0 = warp_n * 64 + (lane & 3) * 2;        // tile-local col
    const int col0 = bn * BLK_N + cl0;
#pragma unroll
    for (int mi = 0; mi < 2; mi++) {
#pragma unroll
        for (int nn = 0; nn < 8; nn++) {
            const int cl = cl0 + nn * 8;
            const float b0 = biasS[cl];
            const float b1 = biasS[cl + 1];
            const int c = col0 + nn * 8;
            const int r = row0 + mi * 16;
            float v00 = fmaxf(acc[mi][nn][0] + b0, 0.f);
            float v01 = fmaxf(acc[mi][nn][1] + b1, 0.f);
            float v10 = fmaxf(acc[mi][nn][2] + b0, 0.f);
            float v11 = fmaxf(acc[mi][nn][3] + b1, 0.f);
            if (is_last) {
                float2 u0; u0.x = v00; u0.y = v01;
                float2 u1; u1.x = v10; u1.y = v11;
                *reinterpret_cast<float2*>(outF + (size_t)r * NDIM + c) = u0;
                *reinterpret_cast<float2*>(outF + (size_t)(r + 8) * NDIM + c) = u1;
            } else {
                __half2 h0 = __floats2half2_rn(v00, v01);
                __half2 h1 = __floats2half2_rn(v10, v11);
                *reinterpret_cast<__half2*>(nextA + (size_t)r * NDIM + c) = h0;
                *reinterpret_cast<__half2*>(nextA + (size_t)(r + 8) * NDIM + c) = h1;
            }
        }
    }

    // ---------------- signal completion (not needed for last layer) ----------------
    if (!is_last) {
        __syncthreads();                 // all stores in this CTA done
        if (tid == 0) {
            __threadfence();             // make them visible device-wide
            atomicAdd(&g_ready[layer * TILES_M + bm], 1);
        }
    }
}

// ---------------------------------------------------------------------------
// launch
// ---------------------------------------------------------------------------
extern "C" void kernel_launch(void* const* d_in, const int* in_sizes, int n_in,
                              void* d_out, int out_size) {
    (void)in_sizes; (void)n_in; (void)out_size;
    const float* x = (const float*)d_in[0];
    const float* W = (const float*)d_in[1];
    float* out = (float*)d_out;

    void *pxh, *pa, *pwh;
    cudaGetSymbolAddress(&pxh, g_xH);
    cudaGetSymbolAddress(&pa, g_a);
    cudaGetSymbolAddress(&pwh, g_Wh);
    __half* xH = (__half*)pxh;
    __half* aP = (__half*)pa;
    __half* Wh = (__half*)pwh;

    // 1) single prep launch: zero flags + convert x and W
    prep_kernel<<<PREP_CTAS, 256>>>((const float4*)x, (const float4*)W);

    // 2) smem opt-in
    cudaFuncSetAttribute(fused_mlp_kernel,
                         cudaFuncAttributeMaxDynamicSharedMemorySize, SMEM_TOTAL);

    // 3) single fused gemm launch: 7 layers x 512 tiles
    fused_mlp_kernel<<<DEPTH * TILES_L, 256, SMEM_TOTAL>>>(xH, aP, Wh, W, out);
}

// round 17
// speedup vs baseline: 1.0083x; 1.0083x over previous
#include <cuda_runtime.h>
#include <cuda_fp16.h>
#include <cstdint>

// ---------------------------------------------------------------------------
// Problem dims
// ---------------------------------------------------------------------------
#define BDIM 4096
#define NDIM 2048
#define KDIM 2048
#define DEPTH 7
#define WROWS 2049            // K rows + bias row

// ---------------------------------------------------------------------------
// Tiling: 128x128 CTA tile, 8 warps (32x64 warp tile), K-chunks of 64,
// 3-stage cp.async pipeline, SW128 swizzle, hoisted addresses.
// ONE fused gemm grid (7 layers x 512 tiles, R15 kernel) +
// ONE flat prep kernel (R16 grid-stride/__ldcs version).
// ---------------------------------------------------------------------------
#define BLK_M 128
#define BLK_N 128
#define BLK_K 64
#define CHUNKS (KDIM / BLK_K)     // 32
#define STAGES 3

#define TILES_M (BDIM / BLK_M)    // 32
#define TILES_N (NDIM / BLK_N)    // 16
#define TILES_L (TILES_M * TILES_N)  // 512

#define A_BYTES 16384
#define B_SUB_BYTES 8192
#define STAGE_BYTES (A_BYTES + 2 * B_SUB_BYTES)      // 32768
#define SMEM_BYTES (STAGES * STAGE_BYTES)            // 98304 (2 CTAs/SM)

// prep sizes (float4 units)
#define X_F4 (BDIM * NDIM / 4)               // 2097152
#define W_F4_ALL (DEPTH * WROWS * NDIM / 4)  // 7343616
#define PREP_F4 (X_F4 + W_F4_ALL)            // 9440768
#define PREP_PER 4                           // float4 per thread
#define PREP_CTAS ((PREP_F4 + 256 * PREP_PER - 1) / (256 * PREP_PER))  // 9220

// ---------------------------------------------------------------------------
// Device scratch (allocation-free rule)
// ---------------------------------------------------------------------------
__device__ __half g_xH[(size_t)BDIM * NDIM];
__device__ __half g_a[2][(size_t)BDIM * NDIM];
__device__ __half g_Wh[(size_t)DEPTH * WROWS * NDIM];
__device__ int g_ready[DEPTH * TILES_M];   // completed bn-tiles per (layer, bm)

// ---------------------------------------------------------------------------
// helpers
// ---------------------------------------------------------------------------
__device__ __forceinline__ void ldsm4_a(uint32_t (&r)[4], uint32_t addr) {
    asm volatile("ldmatrix.sync.aligned.m8n8.x4.shared.b16 {%0,%1,%2,%3}, [%4];\n"
                 : "=r"(r[0]), "=r"(r[1]), "=r"(r[2]), "=r"(r[3]) : "r"(addr));
}

__device__ __forceinline__ void ldsm4t_a(uint32_t (&r)[4], uint32_t addr) {
    asm volatile("ldmatrix.sync.aligned.m8n8.x4.trans.shared.b16 {%0,%1,%2,%3}, [%4];\n"
                 : "=r"(r[0]), "=r"(r[1]), "=r"(r[2]), "=r"(r[3]) : "r"(addr));
}

__device__ __forceinline__ void mma_f16(float (&d)[4], const uint32_t (&a)[4], const uint32_t* b) {
    asm volatile(
        "mma.sync.aligned.m16n8k16.row.col.f32.f16.f16.f32 "
        "{%0,%1,%2,%3}, {%4,%5,%6,%7}, {%8,%9}, {%0,%1,%2,%3};\n"
        : "+f"(d[0]), "+f"(d[1]), "+f"(d[2]), "+f"(d[3])
        : "r"(a[0]), "r"(a[1]), "r"(a[2]), "r"(a[3]), "r"(b[0]), "r"(b[1]));
}

__device__ __forceinline__ void cp16(uint32_t dst, const void* src) {
    asm volatile("cp.async.cg.shared.global [%0], [%1], 16;" :: "r"(dst), "l"(src));
}
#define CP_COMMIT() asm volatile("cp.async.commit_group;" ::: "memory")
#define CP_WAIT(n)  asm volatile("cp.async.wait_group %0;" :: "n"(n) : "memory")

__device__ __forceinline__ uint2 cvt4(float4 v) {
    __half2 H0 = __floats2half2_rn(v.x, v.y);
    __half2 H1 = __floats2half2_rn(v.z, v.w);
    uint2 u; u.x = *(uint32_t*)&H0; u.y = *(uint32_t*)&H1;
    return u;
}

// ---------------------------------------------------------------------------
// Prep kernel (R16 version): zero flags (CTA 0) + convert x and all W layers.
// Grid-stride, 4 float4/thread, evict-first loads (single-use fp32 stream).
// ---------------------------------------------------------------------------
__global__ void prep_kernel(const float4* __restrict__ xF,
                            const float4* __restrict__ Wfp) {
    const int tid = threadIdx.x;
    if (blockIdx.x == 0 && tid < DEPTH * TILES_M)
        g_ready[tid] = 0;

    const int base = (blockIdx.x * 256) * PREP_PER + tid;
#pragma unroll
    for (int q = 0; q < PREP_PER; q++) {
        const int i = base + q * 256;
        if (i < X_F4) {
            reinterpret_cast<uint2*>(g_xH)[i] = cvt4(__ldcs(xF + i));
        } else if (i < PREP_F4) {
            const int j = i - X_F4;
            reinterpret_cast<uint2*>(g_Wh)[j] = cvt4(__ldcs(Wfp + j));
        }
    }
}

// ---------------------------------------------------------------------------
// Fused 7-layer gemm kernel (R15 version, bias via __ldg in epilogue).
// CTA bid -> (layer, bm, bn).
// ---------------------------------------------------------------------------
__global__ __launch_bounds__(256, 2)
void fused_mlp_kernel(const __half* __restrict__ xH,
                      __half* __restrict__ act,      // [2][B*N]
                      const __half* __restrict__ Wh, // [DEPTH][WROWS][N]
                      const float* __restrict__ Wfp, // original fp32 W (for bias)
                      float* __restrict__ outF)
{
    extern __shared__ __align__(128) __half smem[];
    const uint32_t sb = (uint32_t)__cvta_generic_to_shared(smem);

    const int bid = blockIdx.x;
    const int layer = bid >> 9;          // /512
    const int t = bid & 511;
    const int bm = t >> 4;               // 0..31
    const int bn = t & 15;               // 0..15
    const int is_last = (layer == DEPTH - 1);

    const size_t ACT = (size_t)BDIM * NDIM;
    const __half* A = (layer == 0) ? xH : act + ((size_t)((layer - 1) & 1)) * ACT;
    __half* nextA = act + ((size_t)(layer & 1)) * ACT;
    const __half* B = Wh + (size_t)layer * WROWS * NDIM;
    const float* bias = Wfp + (size_t)layer * WROWS * NDIM + (size_t)KDIM * NDIM;

    const int tid = threadIdx.x;
    const int lane = tid & 31;
    const int warp = tid >> 5;
    const int warp_m = warp >> 1;   // 0..3 (32 rows)
    const int warp_n = warp & 1;    // 0..1 (64 cols -> B subtile)

    // ---------------- wait for input rowblock (layers > 0) ----------------
    if (layer > 0) {
        if (tid == 0) {
            volatile int* cnt = &g_ready[(layer - 1) * TILES_M + bm];
            while (*cnt < TILES_N) __nanosleep(128);
            __threadfence();
        }
        __syncthreads();
    }

    // ---------------- precomputed cp.async addresses ----------------
    const int a_row = tid >> 1;
    const int a_gb16 = (tid & 1) * 64;
    const uint32_t a_xor = (uint32_t)((a_row & 7) << 4);
    const uint32_t dstA0 = sb + (uint32_t)(a_row * 128) + (uint32_t)(a_gb16 ^ a_xor);
    const __half* gA = A + (size_t)(bm * BLK_M + a_row) * KDIM + (tid & 1) * 32;

    const int b_r0 = tid >> 4;
    const int b_gc = tid & 15;
    const uint32_t b_xor = (uint32_t)((b_r0 & 7) << 4);
    const uint32_t dstB0 = sb + (uint32_t)A_BYTES + (uint32_t)((b_gc >> 3) * B_SUB_BYTES)
                         + (uint32_t)(b_r0 * 128) + ((uint32_t)((b_gc & 7) * 16) ^ b_xor);
    const __half* gB = B + (size_t)b_r0 * NDIM + bn * BLK_N + b_gc * 8;

    auto load_stage = [&](int s, const __half* gA_c, const __half* gB_c) {
        const uint32_t sbase = (uint32_t)(s * STAGE_BYTES);
#pragma unroll
        for (int q = 0; q < 4; q++)
            cp16((dstA0 ^ (uint32_t)(q * 16)) + sbase, gA_c + q * 8);
#pragma unroll
        for (int p = 0; p < 4; p++)
            cp16(dstB0 + sbase + (uint32_t)(p * 2048), gB_c + (size_t)(p * 16) * NDIM);
        CP_COMMIT();
    };

    // ---------------- ldsm base addresses (stage-relative) ----------------
    const uint32_t hi16 = (uint32_t)((lane >> 4) << 4);
    uint32_t aAddr[2];
#pragma unroll
    for (int mi = 0; mi < 2; mi++) {
        const int r = warp_m * 32 + mi * 16 + (lane & 15);
        aAddr[mi] = sb + (uint32_t)(r * 128) + (hi16 ^ (uint32_t)((r & 7) << 4));
    }
    const uint32_t bAddr0 = sb + (uint32_t)A_BYTES + (uint32_t)(warp_n * B_SUB_BYTES)
                          + (uint32_t)((lane & 15) * 128)
                          + (hi16 ^ (uint32_t)((lane & 7) << 4));

    float acc[2][8][4];
#pragma unroll
    for (int i = 0; i < 2; i++)
#pragma unroll
        for (int j = 0; j < 8; j++)
#pragma unroll
            for (int k = 0; k < 4; k++) acc[i][j][k] = 0.f;

    auto compute_stage = [&](int s) {
        const uint32_t sbase = (uint32_t)(s * STAGE_BYTES);
#pragma unroll
        for (int kk = 0; kk < 4; kk++) {
            uint32_t ah[2][4];
#pragma unroll
            for (int mi = 0; mi < 2; mi++)
                ldsm4_a(ah[mi], (aAddr[mi] ^ (uint32_t)(kk << 5)) + sbase);
#pragma unroll
            for (int ng = 0; ng < 4; ng++) {
                uint32_t bh[4];
                ldsm4t_a(bh, (bAddr0 ^ (uint32_t)(ng << 5)) + sbase + (uint32_t)(kk * 2048));
#pragma unroll
                for (int mi = 0; mi < 2; mi++)
#pragma unroll
                    for (int h = 0; h < 2; h++)
                        mma_f16(acc[mi][ng * 2 + h], ah[mi], &bh[h * 2]);
            }
        }
    };

    // ---------------- 3-stage pipeline ----------------
    const __half* gA_c = gA;
    const __half* gB_c = gB;
    load_stage(0, gA_c, gB_c);
    gA_c += BLK_K; gB_c += (size_t)BLK_K * NDIM;
    load_stage(1, gA_c, gB_c);
    gA_c += BLK_K; gB_c += (size_t)BLK_K * NDIM;
#pragma unroll 1
    for (int c = 0; c < CHUNKS; c++) {
        CP_WAIT(1);
        __syncthreads();
        compute_stage(c % STAGES);
        if (c + 2 < CHUNKS) {
            load_stage((c + 2) % STAGES, gA_c, gB_c);
            gA_c += BLK_K; gB_c += (size_t)BLK_K * NDIM;
        }
    }

    // ---------------- epilogue: bias + ReLU + store ----------------
    const int row0 = bm * BLK_M + warp_m * 32 + (lane >> 2);
    const int col0 = bn * BLK_N + warp_n * 64 + (lane & 3) * 2;
#pragma unroll
    for (int mi = 0; mi < 2; mi++) {
#pragma unroll
        for (int nn = 0; nn < 8; nn++) {
            const int c = col0 + nn * 8;
            const float b0 = __ldg(bias + c);
            const float b1 = __ldg(bias + c + 1);
            const int r = row0 + mi * 16;
            float v00 = fmaxf(acc[mi][nn][0] + b0, 0.f);
            float v01 = fmaxf(acc[mi][nn][1] + b1, 0.f);
            float v10 = fmaxf(acc[mi][nn][2] + b0, 0.f);
            float v11 = fmaxf(acc[mi][nn][3] + b1, 0.f);
            if (is_last) {
                float2 u0; u0.x = v00; u0.y = v01;
                float2 u1; u1.x = v10; u1.y = v11;
                *reinterpret_cast<float2*>(outF + (size_t)r * NDIM + c) = u0;
                *reinterpret_cast<float2*>(outF + (size_t)(r + 8) * NDIM + c) = u1;
            } else {
                __half2 h0 = __floats2half2_rn(v00, v01);
                __half2 h1 = __floats2half2_rn(v10, v11);
                *reinterpret_cast<__half2*>(nextA + (size_t)r * NDIM + c) = h0;
                *reinterpret_cast<__half2*>(nextA + (size_t)(r + 8) * NDIM + c) = h1;
            }
        }
    }

    // ---------------- signal completion (not needed for last layer) ----------------
    if (!is_last) {
        __syncthreads();                 // all stores in this CTA done
        if (tid == 0) {
            __threadfence();             // make them visible device-wide
            atomicAdd(&g_ready[layer * TILES_M + bm], 1);
        }
    }
}

// ---------------------------------------------------------------------------
// launch
// ---------------------------------------------------------------------------
extern "C" void kernel_launch(void* const* d_in, const int* in_sizes, int n_in,
                              void* d_out, int out_size) {
    (void)in_sizes; (void)n_in; (void)out_size;
    const float* x = (const float*)d_in[0];
    const float* W = (const float*)d_in[1];
    float* out = (float*)d_out;

    void *pxh, *pa, *pwh;
    cudaGetSymbolAddress(&pxh, g_xH);
    cudaGetSymbolAddress(&pa, g_a);
    cudaGetSymbolAddress(&pwh, g_Wh);
    __half* xH = (__half*)pxh;
    __half* aP = (__half*)pa;
    __half* Wh = (__half*)pwh;

    // 1) single prep launch: zero flags + convert x and W
    prep_kernel<<<PREP_CTAS, 256>>>((const float4*)x, (const float4*)W);

    // 2) smem opt-in
    cudaFuncSetAttribute(fused_mlp_kernel,
                         cudaFuncAttributeMaxDynamicSharedMemorySize, SMEM_BYTES);

    // 3) single fused gemm launch: 7 layers x 512 tiles
    fused_mlp_kernel<<<DEPTH * TILES_L, 256, SMEM_BYTES>>>(xH, aP, Wh, W, out);
}